// round 3
// baseline (speedup 1.0000x reference)
#include <cuda_runtime.h>
#include <math.h>

#define N_NODES 50000
#define N_EDGES 600000
#define F 128
#define NGRAPH 1024

// ---------------- scratch ----------------
__device__ float d_bufA[N_NODES * F];
__device__ float d_bufB[N_NODES * F];
__device__ int   d_deg[N_NODES];
__device__ float d_dinv[N_NODES];
__device__ int   d_rowptr[N_NODES + 1];
__device__ int   d_fill[N_NODES];
__device__ int   d_col[N_EDGES];
__device__ int   d_bsum[1024];
__device__ int   d_gcnt[NGRAPH];
__device__ int   d_gptr[NGRAPH + 1];
__device__ float d_pool[NGRAPH * 2 * F];

// ---------------- setup kernels ----------------
__global__ void k_init() {
    int i = blockIdx.x * blockDim.x + threadIdx.x;
    int stride = gridDim.x * blockDim.x;
    for (int j = i; j < N_NODES; j += stride) d_deg[j] = 0;
    for (int j = i; j < NGRAPH; j += stride) d_gcnt[j] = 0;
}

// one kernel: edge histogram + batch histogram
__global__ void k_hist(const int* __restrict__ ei, const int* __restrict__ bi) {
    int i = blockIdx.x * blockDim.x + threadIdx.x;
    if (i < N_EDGES) atomicAdd(&d_deg[ei[N_EDGES + i]], 1);
    if (i < N_NODES) atomicAdd(&d_gcnt[bi[i]], 1);
}

// exclusive scan partials; optionally also emits dinv = rsqrt(deg+1)
__global__ void k_scan_partial(const int* __restrict__ in, int* __restrict__ out,
                               int* __restrict__ bsums, int n, int do_dinv) {
    __shared__ int s[1024];
    int t = threadIdx.x;
    int i = blockIdx.x * 1024 + t;
    int v = (i < n) ? in[i] : 0;
    if (do_dinv && i < n) d_dinv[i] = rsqrtf((float)v + 1.0f);
    s[t] = v;
    __syncthreads();
    for (int off = 1; off < 1024; off <<= 1) {
        int u = (t >= off) ? s[t - off] : 0;
        __syncthreads();
        s[t] += u;
        __syncthreads();
    }
    if (i < n) out[i] = s[t] - v;
    if (t == 1023) bsums[blockIdx.x] = s[1023];
}

__global__ void k_scan_top(int* __restrict__ b, int n, int* __restrict__ total) {
    __shared__ int s[1024];
    int t = threadIdx.x;
    int v = (t < n) ? b[t] : 0;
    s[t] = v;
    __syncthreads();
    for (int off = 1; off < 1024; off <<= 1) {
        int u = (t >= off) ? s[t - off] : 0;
        __syncthreads();
        s[t] += u;
        __syncthreads();
    }
    if (t < n) b[t] = s[t] - v;
    if (t == 1023) total[0] = s[1023];
}

// add block offsets; optionally also seeds d_fill with the final rowptr value
__global__ void k_scan_add(int* __restrict__ out, const int* __restrict__ bsums,
                           int n, int do_fill) {
    int i = blockIdx.x * 1024 + threadIdx.x;
    if (i < n) {
        int v = out[i] + bsums[blockIdx.x];
        out[i] = v;
        if (do_fill) d_fill[i] = v;
    }
}

__global__ void k_fill(const int* __restrict__ ei) {
    int e = blockIdx.x * blockDim.x + threadIdx.x;
    if (e < N_EDGES) {
        int dst = ei[N_EDGES + e];
        int p = atomicAdd(&d_fill[dst], 1);
        d_col[p] = ei[e];
    }
}

// ---------------- GEMM: O[v,:] = dinv[v] * (X[v,:] @ W) ----------------
// 128x128 tile, 256 threads, 8x8 micro-tile, BK=16, register-prefetch of next chunk.
__device__ __forceinline__ void fma4(float4& a, float s, const float4& v) {
    a.x = fmaf(s, v.x, a.x);
    a.y = fmaf(s, v.y, a.y);
    a.z = fmaf(s, v.z, a.z);
    a.w = fmaf(s, v.w, a.w);
}

#define BK 16

__global__ __launch_bounds__(256) void k_gemm(const float* __restrict__ X,
                                              const float* __restrict__ W,
                                              float* __restrict__ O) {
    __shared__ float xs[BK][128];   // [k][row]
    __shared__ float ws[BK][128];   // [k][col]
    const int tid = threadIdx.x;
    const int tx = tid & 15;        // col group
    const int ty = tid >> 4;        // row group
    const int row0 = blockIdx.x * 128;

    const float4* X4 = (const float4*)X;
    const float4* W4 = (const float4*)W;

    // loader roles
    const int xrow = tid >> 1;            // 0..127
    const int xkh  = tid & 1;             // which 8-k half
    const int widx = tid * 2;             // 2 float4 of W chunk per thread
    const int wk   = widx >> 5;           // 0..15 within chunk
    const int wc4  = widx & 31;           // col4

    float4 acc[8][2];
#pragma unroll
    for (int i = 0; i < 8; i++) {
        acc[i][0] = make_float4(0.f, 0.f, 0.f, 0.f);
        acc[i][1] = make_float4(0.f, 0.f, 0.f, 0.f);
    }

    // prefetch chunk 0 into registers
    float4 px0, px1, pw0, pw1;
    {
        int gr = row0 + xrow;
        bool ok = gr < N_NODES;
        px0 = ok ? X4[(size_t)gr * 32 + xkh * 2 + 0] : make_float4(0.f, 0.f, 0.f, 0.f);
        px1 = ok ? X4[(size_t)gr * 32 + xkh * 2 + 1] : make_float4(0.f, 0.f, 0.f, 0.f);
        pw0 = W4[(size_t)wk * 32 + wc4];
        pw1 = W4[(size_t)wk * 32 + wc4 + 1];
    }

    for (int kk = 0; kk < 128; kk += BK) {
        // store prefetched chunk to smem
        {
            int kb = xkh * 8;
            xs[kb + 0][xrow] = px0.x; xs[kb + 1][xrow] = px0.y;
            xs[kb + 2][xrow] = px0.z; xs[kb + 3][xrow] = px0.w;
            xs[kb + 4][xrow] = px1.x; xs[kb + 5][xrow] = px1.y;
            xs[kb + 6][xrow] = px1.z; xs[kb + 7][xrow] = px1.w;
            ((float4*)ws[wk])[wc4] = pw0;
            ((float4*)ws[wk])[wc4 + 1] = pw1;
        }
        __syncthreads();

        // prefetch next chunk (overlaps with compute below)
        int kn = kk + BK;
        if (kn < 128) {
            int gr = row0 + xrow;
            bool ok = gr < N_NODES;
            int xo = (kn >> 2) + xkh * 2;
            px0 = ok ? X4[(size_t)gr * 32 + xo + 0] : make_float4(0.f, 0.f, 0.f, 0.f);
            px1 = ok ? X4[(size_t)gr * 32 + xo + 1] : make_float4(0.f, 0.f, 0.f, 0.f);
            pw0 = W4[(size_t)(kn + wk) * 32 + wc4];
            pw1 = W4[(size_t)(kn + wk) * 32 + wc4 + 1];
        }

#pragma unroll
        for (int k = 0; k < BK; k++) {
            float4 a0 = *(const float4*)&xs[k][ty * 8];
            float4 a1 = *(const float4*)&xs[k][ty * 8 + 4];
            float4 b0 = *(const float4*)&ws[k][tx * 8];
            float4 b1 = *(const float4*)&ws[k][tx * 8 + 4];
            fma4(acc[0][0], a0.x, b0); fma4(acc[0][1], a0.x, b1);
            fma4(acc[1][0], a0.y, b0); fma4(acc[1][1], a0.y, b1);
            fma4(acc[2][0], a0.z, b0); fma4(acc[2][1], a0.z, b1);
            fma4(acc[3][0], a0.w, b0); fma4(acc[3][1], a0.w, b1);
            fma4(acc[4][0], a1.x, b0); fma4(acc[4][1], a1.x, b1);
            fma4(acc[5][0], a1.y, b0); fma4(acc[5][1], a1.y, b1);
            fma4(acc[6][0], a1.z, b0); fma4(acc[6][1], a1.z, b1);
            fma4(acc[7][0], a1.w, b0); fma4(acc[7][1], a1.w, b1);
        }
        __syncthreads();
    }

    float4* O4 = (float4*)O;
#pragma unroll
    for (int i = 0; i < 8; i++) {
        int r = row0 + ty * 8 + i;
        if (r < N_NODES) {
            float s = d_dinv[r];
            float4 a = acc[i][0];
            a.x *= s; a.y *= s; a.z *= s; a.w *= s;
            float4 b = acc[i][1];
            b.x *= s; b.y *= s; b.z *= s; b.w *= s;
            O4[(size_t)r * 32 + tx * 2] = a;
            O4[(size_t)r * 32 + tx * 2 + 1] = b;
        }
    }
}

// ---------------- aggregation: out[v] = relu(dinv[v]*(g[v] + sum g[src]) + b) ----------------
__global__ __launch_bounds__(256) void k_agg(const float* __restrict__ Gf,
                                             const float* __restrict__ b,
                                             float* __restrict__ O) {
    int gw = (blockIdx.x * blockDim.x + threadIdx.x) >> 5;
    int lane = threadIdx.x & 31;
    if (gw >= N_NODES) return;
    const float4* G4 = (const float4*)Gf;
    float4 a0 = G4[(size_t)gw * 32 + lane];  // self loop
    float4 a1 = make_float4(0.f, 0.f, 0.f, 0.f);
    float4 a2 = make_float4(0.f, 0.f, 0.f, 0.f);
    float4 a3 = make_float4(0.f, 0.f, 0.f, 0.f);
    int beg = d_rowptr[gw], end = d_rowptr[gw + 1];
    int e = beg;
    for (; e + 4 <= end; e += 4) {
        int s0 = d_col[e], s1 = d_col[e + 1], s2 = d_col[e + 2], s3 = d_col[e + 3];
        float4 v0 = G4[(size_t)s0 * 32 + lane];
        float4 v1 = G4[(size_t)s1 * 32 + lane];
        float4 v2 = G4[(size_t)s2 * 32 + lane];
        float4 v3 = G4[(size_t)s3 * 32 + lane];
        a0.x += v0.x; a0.y += v0.y; a0.z += v0.z; a0.w += v0.w;
        a1.x += v1.x; a1.y += v1.y; a1.z += v1.z; a1.w += v1.w;
        a2.x += v2.x; a2.y += v2.y; a2.z += v2.z; a2.w += v2.w;
        a3.x += v3.x; a3.y += v3.y; a3.z += v3.z; a3.w += v3.w;
    }
    for (; e < end; e++) {
        int s = d_col[e];
        float4 v = G4[(size_t)s * 32 + lane];
        a0.x += v.x; a0.y += v.y; a0.z += v.z; a0.w += v.w;
    }
    a0.x += a1.x + a2.x + a3.x;
    a0.y += a1.y + a2.y + a3.y;
    a0.z += a1.z + a2.z + a3.z;
    a0.w += a1.w + a2.w + a3.w;
    float dv = d_dinv[gw];
    float4 bb = ((const float4*)b)[lane];
    float4 r;
    r.x = fmaxf(fmaf(dv, a0.x, bb.x), 0.f);
    r.y = fmaxf(fmaf(dv, a0.y, bb.y), 0.f);
    r.z = fmaxf(fmaf(dv, a0.z, bb.z), 0.f);
    r.w = fmaxf(fmaf(dv, a0.w, bb.w), 0.f);
    ((float4*)O)[(size_t)gw * 32 + lane] = r;
}

// ---------------- pooling ----------------
__global__ __launch_bounds__(256) void k_pool(const float* __restrict__ H) {
    int gw = (blockIdx.x * blockDim.x + threadIdx.x) >> 5;
    int lane = threadIdx.x & 31;
    if (gw >= NGRAPH) return;
    int beg = d_gptr[gw], end = d_gptr[gw + 1];
    const float4* H4 = (const float4*)H;
    float4 mx = make_float4(0.f, 0.f, 0.f, 0.f);
    float4 sm = make_float4(0.f, 0.f, 0.f, 0.f);
    for (int v = beg; v < end; v++) {
        float4 x = H4[(size_t)v * 32 + lane];
        mx.x = fmaxf(mx.x, x.x); mx.y = fmaxf(mx.y, x.y);
        mx.z = fmaxf(mx.z, x.z); mx.w = fmaxf(mx.w, x.w);
        sm.x += x.x; sm.y += x.y; sm.z += x.z; sm.w += x.w;
    }
    int cnt = end - beg;
    float inv = 1.f / (float)(cnt > 0 ? cnt : 1);
    float4* P4 = (float4*)d_pool;
    P4[gw * 64 + lane] = mx;
    float4 mn = make_float4(sm.x * inv, sm.y * inv, sm.z * inv, sm.w * inv);
    P4[gw * 64 + 32 + lane] = mn;
}

// ---------------- MLP head ----------------
__global__ __launch_bounds__(128) void k_mlp(const float* __restrict__ Wl1, const float* __restrict__ bl1,
                                             const float* __restrict__ Wl2, const float* __restrict__ bl2,
                                             const float* __restrict__ Wl3, const float* __restrict__ bl3,
                                             float* __restrict__ out) {
    __shared__ float gv[256];
    __shared__ float o1[128];
    __shared__ float red[128];
    int g = blockIdx.x;
    int t = threadIdx.x;
    gv[t] = d_pool[g * 256 + t];
    gv[t + 128] = d_pool[g * 256 + 128 + t];
    __syncthreads();
    float a = bl1[t];
#pragma unroll 8
    for (int k = 0; k < 256; k++) a = fmaf(gv[k], Wl1[k * 128 + t], a);
    o1[t] = fmaxf(a, 0.f);
    __syncthreads();
    float c = bl2[t];
#pragma unroll 8
    for (int k = 0; k < 128; k++) c = fmaf(o1[k], Wl2[k * 128 + t], c);
    c = fmaxf(c, 0.f);
    red[t] = c * Wl3[t];
    __syncthreads();
    for (int off = 64; off > 0; off >>= 1) {
        if (t < off) red[t] += red[t + off];
        __syncthreads();
    }
    if (t == 0) out[g] = 1.f / (1.f + expf(-(red[0] + bl3[0])));
}

// ---------------- launch ----------------
extern "C" void kernel_launch(void* const* d_in, const int* in_sizes, int n_in,
                              void* d_out, int out_size) {
    const float* x   = (const float*)d_in[0];
    const int*   ei  = (const int*)d_in[1];
    const int*   bi  = (const int*)d_in[2];
    const float* W0  = (const float*)d_in[3];
    const float* b0  = (const float*)d_in[4];
    const float* W1  = (const float*)d_in[5];
    const float* b1  = (const float*)d_in[6];
    const float* W2  = (const float*)d_in[7];
    const float* b2  = (const float*)d_in[8];
    const float* Wl1 = (const float*)d_in[9];
    const float* bl1 = (const float*)d_in[10];
    const float* Wl2 = (const float*)d_in[11];
    const float* bl2 = (const float*)d_in[12];
    const float* Wl3 = (const float*)d_in[13];
    const float* bl3 = (const float*)d_in[14];
    float* out = (float*)d_out;

    void* p;
    cudaGetSymbolAddress(&p, d_deg);    int* deg = (int*)p;
    cudaGetSymbolAddress(&p, d_rowptr); int* rowptr = (int*)p;
    cudaGetSymbolAddress(&p, d_bsum);   int* bsum = (int*)p;
    cudaGetSymbolAddress(&p, d_gcnt);   int* gcnt = (int*)p;
    cudaGetSymbolAddress(&p, d_gptr);   int* gptr = (int*)p;
    cudaGetSymbolAddress(&p, d_bufA);   float* bufA = (float*)p;
    cudaGetSymbolAddress(&p, d_bufB);   float* bufB = (float*)p;

    // ---- graph structure ----
    k_init<<<64, 256>>>();
    k_hist<<<(N_EDGES + 255) / 256, 256>>>(ei, bi);

    const int NB = (N_NODES + 1023) / 1024;  // 49
    k_scan_partial<<<NB, 1024>>>(deg, rowptr, bsum, N_NODES, 1);
    k_scan_top<<<1, 1024>>>(bsum, NB, rowptr + N_NODES);
    k_scan_add<<<NB, 1024>>>(rowptr, bsum, N_NODES, 1);
    k_fill<<<(N_EDGES + 255) / 256, 256>>>(ei);

    k_scan_partial<<<1, 1024>>>(gcnt, gptr, bsum, NGRAPH, 0);
    k_scan_top<<<1, 1024>>>(bsum, 1, gptr + NGRAPH);
    k_scan_add<<<1, 1024>>>(gptr, bsum, NGRAPH, 0);

    // ---- 3 GCN layers ----
    const int gemmGrid = (N_NODES + 127) / 128;
    const int aggGrid = (N_NODES * 32 + 255) / 256;
    k_gemm<<<gemmGrid, 256>>>(x, W0, bufB);
    k_agg<<<aggGrid, 256>>>(bufB, b0, bufA);
    k_gemm<<<gemmGrid, 256>>>(bufA, W1, bufB);
    k_agg<<<aggGrid, 256>>>(bufB, b1, bufA);
    k_gemm<<<gemmGrid, 256>>>(bufA, W2, bufB);
    k_agg<<<aggGrid, 256>>>(bufB, b2, bufA);

    // ---- pooling + head ----
    k_pool<<<(NGRAPH * 32 + 255) / 256, 256>>>(bufA);
    k_mlp<<<NGRAPH, 128>>>(Wl1, bl1, Wl2, bl2, Wl3, bl3, out);
}